// round 14
// baseline (speedup 1.0000x reference)
#include <cuda_runtime.h>
#include <cuda_fp16.h>
#include <cstdint>

static constexpr int E_EDGES = 250000;
static constexpr int T_E     = 16;
static constexpr int NTILE   = E_EDGES / T_E;   // 15625 exact

#define SQ3f  1.7320508075688772f
#define SQ5f  2.2360679774997896f
#define SQ15f 3.8729833462074170f
#define HSQ3f 0.8660254037844386f

// ---- smem map ----
// Wh: f16[192][72] (27648 B), Wl: +27648  (block-shared)
// 8 warp regions (stride 22016):
//   [0:12800)     wS f32[16][200]  (ALIASES invH f16[16][72] @0 + invL @2304)
//   [12800:22016) stage: 2 slots x 4608 B (one 2-edge pair each)
static constexpr int OFF_WL   = 27648;
static constexpr int OFF_WARP = 55296;
static constexpr int P_STRIDE = 22016;
static constexpr int R_INVL   = 2304;
static constexpr int R_STG    = 12800;
static constexpr int PAIR_B   = 4608;
static constexpr int SMEM_BYTES = OFF_WARP + 8 * P_STRIDE;   // 231424

__device__ __forceinline__ uint32_t smem_u32(const void* p) {
    uint32_t a;
    asm("{ .reg .u64 t; cvta.to.shared.u64 t, %1; cvt.u32.u64 %0, t; }" : "=r"(a) : "l"(p));
    return a;
}
__device__ __forceinline__ void mma16816(float& c0, float& c1, float& c2, float& c3,
                                         uint32_t a0, uint32_t a1, uint32_t a2, uint32_t a3,
                                         uint32_t b0, uint32_t b1) {
    asm volatile("mma.sync.aligned.m16n8k16.row.col.f32.f16.f16.f32 "
                 "{%0,%1,%2,%3}, {%4,%5,%6,%7}, {%8,%9}, {%0,%1,%2,%3};"
                 : "+f"(c0), "+f"(c1), "+f"(c2), "+f"(c3)
                 : "r"(a0), "r"(a1), "r"(a2), "r"(a3), "r"(b0), "r"(b1));
}

__global__ void __launch_bounds__(256, 1)
sh_embed_hmma_p(const float* __restrict__ edge_vec, const float* __restrict__ inv_g,
                const float* __restrict__ Wg, float* __restrict__ out)
{
    extern __shared__ char smem[];
    const int tid = threadIdx.x, lane = tid & 31, wid = tid >> 5;
    const int g = lane >> 2, t = lane & 3;     // mma quad coords

    uint32_t* WhW = (uint32_t*)smem;           // word view, row stride 36 words
    uint32_t* WlW = (uint32_t*)(smem + OFF_WL);

    char* wr = smem + OFF_WARP + wid * P_STRIDE;
    uint32_t* invH = (uint32_t*)wr;            // f16[16][72] (dead after frag load)
    uint32_t* invL = (uint32_t*)(wr + R_INVL);
    float*    wS   = (float*)wr;               // f32[16][200] (aliases inv region)
    char*     stg  = wr + R_STG;
    const uint32_t stgAddr = smem_u32(stg);

    // ---- one-time: W -> f16 hi/lo tiles [col(192)][k(64)], rows padded to 72 f16 ----
    for (int u = tid; u < 192 * 64; u += 256) {
        int col = u >> 6, d = u & 63;
        float v = Wg[d * 192 + col];
        __half h = __float2half_rn(v);
        __half l = __float2half_rn(v - __half2float(h));
        *(__half*)(smem + col * 144 + d * 2)          = h;
        *(__half*)(smem + OFF_WL + col * 144 + d * 2) = l;
    }
    __syncthreads();

    const int half = lane >> 4;                // epilogue: edge within pair
    const int cg   = lane & 15;                // epilogue: 4-channel group
    const int streams = gridDim.x * 8;
    #pragma unroll 1
    for (int tile = blockIdx.x * 8 + wid; tile < NTILE; tile += streams) {
        const int eBase = tile * T_E;
        __syncwarp();   // previous tile's wS reads done before overwriting (alias)

        // ---- stage inv tile as f16 hi/lo (rows padded to 72 f16) ----
        {
            const float4* src = (const float4*)(inv_g + (size_t)eBase * 64);
            #pragma unroll
            for (int r = 0; r < 8; r++) {
                int f = r * 32 + lane, e = f >> 4, i4 = f & 15;
                float4 q = src[f];
                __half2 h01 = __floats2half2_rn(q.x, q.y), h23 = __floats2half2_rn(q.z, q.w);
                float2 g01 = __half22float2(h01), g23 = __half22float2(h23);
                __half2 l01 = __floats2half2_rn(q.x - g01.x, q.y - g01.y);
                __half2 l23 = __floats2half2_rn(q.z - g23.x, q.w - g23.y);
                ((uint2*)invH)[e * 18 + i4] = make_uint2(*(uint32_t*)&h01, *(uint32_t*)&h23);
                ((uint2*)invL)[e * 18 + i4] = make_uint2(*(uint32_t*)&l01, *(uint32_t*)&l23);
            }
        }
        __syncwarp();

        // ---- A fragments (4 k-chunks, hi+lo) into registers ----
        uint32_t Ah[16], Al[16];
        #pragma unroll
        for (int kc = 0; kc < 4; kc++) {
            int b = kc * 8 + t;
            Ah[kc*4+0] = invH[g * 36 + b];      Ah[kc*4+1] = invH[(g + 8) * 36 + b];
            Ah[kc*4+2] = invH[g * 36 + b + 4];  Ah[kc*4+3] = invH[(g + 8) * 36 + b + 4];
            Al[kc*4+0] = invL[g * 36 + b];      Al[kc*4+1] = invL[(g + 8) * 36 + b];
            Al[kc*4+2] = invL[g * 36 + b + 4];  Al[kc*4+3] = invL[(g + 8) * 36 + b + 4];
        }
        __syncwarp();   // frag reads done before wS (alias) is written

        // ---- GEMM: 24 n-chunks in pairs, 3-term f16 split; all 16 rows -> wS ----
        #pragma unroll 1
        for (int np = 0; np < 12; np++) {
            int n0 = np * 16, n1 = n0 + 8;
            float c0 = 0.f, c1 = 0.f, c2 = 0.f, c3 = 0.f;
            float d0 = 0.f, d1 = 0.f, d2 = 0.f, d3 = 0.f;
            #pragma unroll
            for (int kc = 0; kc < 4; kc++) {
                int bi0 = (n0 + g) * 36 + kc * 8 + t;
                int bi1 = (n1 + g) * 36 + kc * 8 + t;
                uint32_t bh0 = WhW[bi0], bh1 = WhW[bi0 + 4];
                uint32_t bl0 = WlW[bi0], bl1 = WlW[bi0 + 4];
                uint32_t ch0 = WhW[bi1], ch1 = WhW[bi1 + 4];
                uint32_t cl0 = WlW[bi1], cl1 = WlW[bi1 + 4];
                const uint32_t* ah = Ah + kc * 4;
                const uint32_t* al = Al + kc * 4;
                mma16816(c0,c1,c2,c3, ah[0],ah[1],ah[2],ah[3], bh0,bh1);
                mma16816(d0,d1,d2,d3, ah[0],ah[1],ah[2],ah[3], ch0,ch1);
                mma16816(c0,c1,c2,c3, al[0],al[1],al[2],al[3], bh0,bh1);
                mma16816(d0,d1,d2,d3, al[0],al[1],al[2],al[3], ch0,ch1);
                mma16816(c0,c1,c2,c3, ah[0],ah[1],ah[2],ah[3], bl0,bl1);
                mma16816(d0,d1,d2,d3, ah[0],ah[1],ah[2],ah[3], cl0,cl1);
            }
            *(float2*)(wS + g * 200 + n0 + 2 * t)       = make_float2(c0, c1);
            *(float2*)(wS + (g + 8) * 200 + n0 + 2 * t) = make_float2(c2, c3);
            *(float2*)(wS + g * 200 + n1 + 2 * t)       = make_float2(d0, d1);
            *(float2*)(wS + (g + 8) * 200 + n1 + 2 * t) = make_float2(d2, d3);
        }
        __syncwarp();   // wS visible to all lanes

        // ---- epilogue: 8 passes of 2 edges; lane = (edge-half, 4-channel group) ----
        #pragma unroll 1
        for (int ep = 0; ep < 8; ++ep) {
            const int eRow = 2 * ep + half;
            // hoist edge_vec load above the slot wait
            const float* vp = edge_vec + (size_t)(eBase + eRow) * 3;
            float vx = vp[0], vy = vp[1], vz = vp[2];

            if (lane == 0) asm volatile("cp.async.bulk.wait_group 1;" ::: "memory");
            __syncwarp();

            float rn = rsqrtf(vx * vx + vy * vy + vz * vz);
            float x = vx * rn, y = vy * rn, z = vz * rn;
            float sh1 = SQ3f * x, sh2 = SQ3f * y, sh3 = SQ3f * z;
            float sh4 = SQ15f * x * z;
            float sh5 = SQ15f * x * y;
            float sh6 = SQ5f  * (y * y - 0.5f * (x * x + z * z));
            float sh7 = SQ15f * y * z;
            float sh8 = (HSQ3f * SQ5f) * (z * z - x * x);

            // 12 contiguous w floats = channels 4cg..4cg+3 (w0,w1,w2 triplets)
            const float4* wv = (const float4*)(wS + eRow * 200 + cg * 12);
            float4 wa = wv[0], wb = wv[1], wc = wv[2];

            float4* sp = (float4*)(stg + (ep & 1) * PAIR_B + (size_t)lane * 144);
            sp[0] = make_float4(wa.x,       sh1 * wa.y, sh2 * wa.y, sh3 * wa.y);
            sp[1] = make_float4(sh4 * wa.z, sh5 * wa.z, sh6 * wa.z, sh7 * wa.z);
            sp[2] = make_float4(sh8 * wa.z, wa.w,       sh1 * wb.x, sh2 * wb.x);
            sp[3] = make_float4(sh3 * wb.x, sh4 * wb.y, sh5 * wb.y, sh6 * wb.y);
            sp[4] = make_float4(sh7 * wb.y, sh8 * wb.y, wb.z,       sh1 * wb.w);
            sp[5] = make_float4(sh2 * wb.w, sh3 * wb.w, sh4 * wc.x, sh5 * wc.x);
            sp[6] = make_float4(sh6 * wc.x, sh7 * wc.x, sh8 * wc.x, wc.y);
            sp[7] = make_float4(sh1 * wc.z, sh2 * wc.z, sh3 * wc.z, sh4 * wc.w);
            sp[8] = make_float4(sh5 * wc.w, sh6 * wc.w, sh7 * wc.w, sh8 * wc.w);
            __syncwarp();

            if (lane == 0) {
                asm volatile("fence.proxy.async.shared::cta;" ::: "memory");
                asm volatile("cp.async.bulk.global.shared::cta.bulk_group [%0], [%1], %2;"
                             :: "l"(out + (size_t)(eBase + 2 * ep) * 576),
                                "r"(stgAddr + (uint32_t)((ep & 1) * PAIR_B)),
                                "n"(PAIR_B) : "memory");
                asm volatile("cp.async.bulk.commit_group;" ::: "memory");
            }
        }
    }

    if (lane == 0) asm volatile("cp.async.bulk.wait_group 0;" ::: "memory");
    __syncwarp();
}

extern "C" void kernel_launch(void* const* d_in, const int* in_sizes, int n_in,
                              void* d_out, int out_size) {
    const float* edge_vec = (const float*)d_in[0];   // [E, 3]
    const float* inv      = (const float*)d_in[1];   // [E, 64]
    const float* W        = (const float*)d_in[2];   // [64, 192]
    float* out            = (float*)d_out;           // [E, 64, 9]
    (void)in_sizes; (void)n_in; (void)out_size;

    int sms = 148;
    cudaDeviceGetAttribute(&sms, cudaDevAttrMultiProcessorCount, 0);
    cudaFuncSetAttribute(sh_embed_hmma_p,
                         cudaFuncAttributeMaxDynamicSharedMemorySize, SMEM_BYTES);
    // 256 threads = 8 independent warp streams per SM, 1 CTA/SM persistent
    sh_embed_hmma_p<<<sms, 256, SMEM_BYTES>>>(edge_vec, inv, W, out);
}

// round 15
// speedup vs baseline: 1.0186x; 1.0186x over previous
#include <cuda_runtime.h>
#include <cuda_fp16.h>
#include <cstdint>

static constexpr int E_EDGES = 250000;
static constexpr int T_E     = 16;
static constexpr int NTILE   = E_EDGES / T_E;   // 15625 exact

#define SQ3f  1.7320508075688772f
#define SQ5f  2.2360679774997896f
#define SQ15f 3.8729833462074170f
#define HSQ3f 0.8660254037844386f

// ---- smem map ----
// Wh: f16[192][72] (27648 B), Wl: +27648  (block-shared)
// 8 warp regions (stride 22016):
//   [0:12800)     wS f32[16][200]  (ALIASES invH f16[16][72] @0 + invL @2304)
//   [12800:22016) stage: 2 slots x 4608 B (one 2-edge pair each)
static constexpr int OFF_WL   = 27648;
static constexpr int OFF_WARP = 55296;
static constexpr int P_STRIDE = 22016;
static constexpr int R_INVL   = 2304;
static constexpr int R_STG    = 12800;
static constexpr int PAIR_B   = 4608;
static constexpr int SMEM_BYTES = OFF_WARP + 8 * P_STRIDE;   // 231424

__device__ __forceinline__ uint32_t smem_u32(const void* p) {
    uint32_t a;
    asm("{ .reg .u64 t; cvta.to.shared.u64 t, %1; cvt.u32.u64 %0, t; }" : "=r"(a) : "l"(p));
    return a;
}
__device__ __forceinline__ void mma16816(float* c,
                                         const uint32_t* a,
                                         uint32_t b0, uint32_t b1) {
    asm volatile("mma.sync.aligned.m16n8k16.row.col.f32.f16.f16.f32 "
                 "{%0,%1,%2,%3}, {%4,%5,%6,%7}, {%8,%9}, {%0,%1,%2,%3};"
                 : "+f"(c[0]), "+f"(c[1]), "+f"(c[2]), "+f"(c[3])
                 : "r"(a[0]), "r"(a[1]), "r"(a[2]), "r"(a[3]), "r"(b0), "r"(b1));
}

__global__ void __launch_bounds__(256, 1)
sh_embed_hmma_i(const float* __restrict__ edge_vec, const float* __restrict__ inv_g,
                const float* __restrict__ Wg, float* __restrict__ out)
{
    extern __shared__ char smem[];
    const int tid = threadIdx.x, lane = tid & 31, wid = tid >> 5;
    const int g = lane >> 2, t = lane & 3;     // mma quad coords

    uint32_t* WhW = (uint32_t*)smem;           // word view, row stride 36 words
    uint32_t* WlW = (uint32_t*)(smem + OFF_WL);

    char* wr = smem + OFF_WARP + wid * P_STRIDE;
    uint32_t* invH = (uint32_t*)wr;            // f16[16][72] (dead after frag load)
    uint32_t* invL = (uint32_t*)(wr + R_INVL);
    float*    wS   = (float*)wr;               // f32[16][200] (aliases inv region)
    char*     stg  = wr + R_STG;
    const uint32_t stgAddr = smem_u32(stg);

    // ---- one-time: W -> f16 hi/lo tiles [col(192)][k(64)], rows padded to 72 f16 ----
    for (int u = tid; u < 192 * 64; u += 256) {
        int col = u >> 6, d = u & 63;
        float v = Wg[d * 192 + col];
        __half h = __float2half_rn(v);
        __half l = __float2half_rn(v - __half2float(h));
        *(__half*)(smem + col * 144 + d * 2)          = h;
        *(__half*)(smem + OFF_WL + col * 144 + d * 2) = l;
    }
    __syncthreads();

    const int half = lane >> 4;                // epilogue: edge within pair
    const int cg   = lane & 15;                // epilogue: 4-channel group
    const int streams = gridDim.x * 8;
    #pragma unroll 1
    for (int tile = blockIdx.x * 8 + wid; tile < NTILE; tile += streams) {
        const int eBase = tile * T_E;
        __syncwarp();   // previous tile's wS reads done before overwriting (alias)

        // ---- stage inv tile as f16 hi/lo (rows padded to 72 f16) ----
        {
            const float4* src = (const float4*)(inv_g + (size_t)eBase * 64);
            #pragma unroll
            for (int r = 0; r < 8; r++) {
                int f = r * 32 + lane, e = f >> 4, i4 = f & 15;
                float4 q = src[f];
                __half2 h01 = __floats2half2_rn(q.x, q.y), h23 = __floats2half2_rn(q.z, q.w);
                float2 g01 = __half22float2(h01), g23 = __half22float2(h23);
                __half2 l01 = __floats2half2_rn(q.x - g01.x, q.y - g01.y);
                __half2 l23 = __floats2half2_rn(q.z - g23.x, q.w - g23.y);
                ((uint2*)invH)[e * 18 + i4] = make_uint2(*(uint32_t*)&h01, *(uint32_t*)&h23);
                ((uint2*)invL)[e * 18 + i4] = make_uint2(*(uint32_t*)&l01, *(uint32_t*)&l23);
            }
        }
        __syncwarp();

        // ---- A fragments (4 k-chunks, hi+lo) into registers ----
        uint32_t Ah[16], Al[16];
        #pragma unroll
        for (int kc = 0; kc < 4; kc++) {
            int b = kc * 8 + t;
            Ah[kc*4+0] = invH[g * 36 + b];      Ah[kc*4+1] = invH[(g + 8) * 36 + b];
            Ah[kc*4+2] = invH[g * 36 + b + 4];  Ah[kc*4+3] = invH[(g + 8) * 36 + b + 4];
            Al[kc*4+0] = invL[g * 36 + b];      Al[kc*4+1] = invL[(g + 8) * 36 + b];
            Al[kc*4+2] = invL[g * 36 + b + 4];  Al[kc*4+3] = invL[(g + 8) * 36 + b + 4];
        }
        __syncwarp();   // frag reads done before wS (alias) is written

        // ---- GEMM: 6 outer iters x 4 n-chunks; per chunk two accumulators
        //      P (AhBh + AlBh, depth 8) and Q (AhBl, depth 4) = 8 parallel chains ----
        #pragma unroll 1
        for (int no = 0; no < 6; no++) {
            const int nb = no * 32;
            float P[4][4], Q[4][4];
            #pragma unroll
            for (int j = 0; j < 4; j++)
                #pragma unroll
                for (int q = 0; q < 4; q++) { P[j][q] = 0.f; Q[j][q] = 0.f; }

            #pragma unroll
            for (int kc = 0; kc < 4; kc++) {
                const uint32_t* ah = Ah + kc * 4;
                const uint32_t* al = Al + kc * 4;
                #pragma unroll
                for (int j = 0; j < 4; j++) {
                    int bi = (nb + j * 8 + g) * 36 + kc * 8 + t;
                    uint32_t bh0 = WhW[bi], bh1 = WhW[bi + 4];
                    uint32_t bl0 = WlW[bi], bl1 = WlW[bi + 4];
                    mma16816(P[j], ah, bh0, bh1);
                    mma16816(Q[j], ah, bl0, bl1);
                    mma16816(P[j], al, bh0, bh1);
                }
            }
            #pragma unroll
            for (int j = 0; j < 4; j++) {
                int n = nb + j * 8;
                *(float2*)(wS + g * 200 + n + 2 * t)
                    = make_float2(P[j][0] + Q[j][0], P[j][1] + Q[j][1]);
                *(float2*)(wS + (g + 8) * 200 + n + 2 * t)
                    = make_float2(P[j][2] + Q[j][2], P[j][3] + Q[j][3]);
            }
        }
        __syncwarp();   // wS visible to all lanes

        // ---- epilogue: 8 passes of 2 edges; lane = (edge-half, 4-channel group) ----
        #pragma unroll 1
        for (int ep = 0; ep < 8; ++ep) {
            const int eRow = 2 * ep + half;
            // hoist edge_vec load above the slot wait
            const float* vp = edge_vec + (size_t)(eBase + eRow) * 3;
            float vx = vp[0], vy = vp[1], vz = vp[2];

            if (lane == 0) asm volatile("cp.async.bulk.wait_group 1;" ::: "memory");
            __syncwarp();

            float rn = rsqrtf(vx * vx + vy * vy + vz * vz);
            float x = vx * rn, y = vy * rn, z = vz * rn;
            float sh1 = SQ3f * x, sh2 = SQ3f * y, sh3 = SQ3f * z;
            float sh4 = SQ15f * x * z;
            float sh5 = SQ15f * x * y;
            float sh6 = SQ5f  * (y * y - 0.5f * (x * x + z * z));
            float sh7 = SQ15f * y * z;
            float sh8 = (HSQ3f * SQ5f) * (z * z - x * x);

            // 12 contiguous w floats = channels 4cg..4cg+3 (w0,w1,w2 triplets)
            const float4* wv = (const float4*)(wS + eRow * 200 + cg * 12);
            float4 wa = wv[0], wb = wv[1], wc = wv[2];

            float4* sp = (float4*)(stg + (ep & 1) * PAIR_B + (size_t)lane * 144);
            sp[0] = make_float4(wa.x,       sh1 * wa.y, sh2 * wa.y, sh3 * wa.y);
            sp[1] = make_float4(sh4 * wa.z, sh5 * wa.z, sh6 * wa.z, sh7 * wa.z);
            sp[2] = make_float4(sh8 * wa.z, wa.w,       sh1 * wb.x, sh2 * wb.x);
            sp[3] = make_float4(sh3 * wb.x, sh4 * wb.y, sh5 * wb.y, sh6 * wb.y);
            sp[4] = make_float4(sh7 * wb.y, sh8 * wb.y, wb.z,       sh1 * wb.w);
            sp[5] = make_float4(sh2 * wb.w, sh3 * wb.w, sh4 * wc.x, sh5 * wc.x);
            sp[6] = make_float4(sh6 * wc.x, sh7 * wc.x, sh8 * wc.x, wc.y);
            sp[7] = make_float4(sh1 * wc.z, sh2 * wc.z, sh3 * wc.z, sh4 * wc.w);
            sp[8] = make_float4(sh5 * wc.w, sh6 * wc.w, sh7 * wc.w, sh8 * wc.w);
            __syncwarp();

            if (lane == 0) {
                asm volatile("fence.proxy.async.shared::cta;" ::: "memory");
                asm volatile("cp.async.bulk.global.shared::cta.bulk_group [%0], [%1], %2;"
                             :: "l"(out + (size_t)(eBase + 2 * ep) * 576),
                                "r"(stgAddr + (uint32_t)((ep & 1) * PAIR_B)),
                                "n"(PAIR_B) : "memory");
                asm volatile("cp.async.bulk.commit_group;" ::: "memory");
            }
        }
    }

    if (lane == 0) asm volatile("cp.async.bulk.wait_group 0;" ::: "memory");
    __syncwarp();
}

extern "C" void kernel_launch(void* const* d_in, const int* in_sizes, int n_in,
                              void* d_out, int out_size) {
    const float* edge_vec = (const float*)d_in[0];   // [E, 3]
    const float* inv      = (const float*)d_in[1];   // [E, 64]
    const float* W        = (const float*)d_in[2];   // [64, 192]
    float* out            = (float*)d_out;           // [E, 64, 9]
    (void)in_sizes; (void)n_in; (void)out_size;

    int sms = 148;
    cudaDeviceGetAttribute(&sms, cudaDevAttrMultiProcessorCount, 0);
    cudaFuncSetAttribute(sh_embed_hmma_i,
                         cudaFuncAttributeMaxDynamicSharedMemorySize, SMEM_BYTES);
    // 256 threads = 8 independent warp streams per SM, 1 CTA/SM persistent
    sh_embed_hmma_i<<<sms, 256, SMEM_BYTES>>>(edge_vec, inv, W, out);
}